// round 9
// baseline (speedup 1.0000x reference)
#include <cuda_runtime.h>
#include <cuda_fp16.h>
#include <cstdint>
#include <cstddef>

// Problem constants
#define DD 1024
#define MROWS 8192

// ---------------------------------------------------------------------------
// Device scratch (allocation-free rule: __device__ globals)
// ---------------------------------------------------------------------------
__device__ unsigned short g_xh[MROWS * DD];   // x as fp16 (16MB)
__device__ unsigned short g_wv16[DD * DD];    // Wv as fp16
__device__ unsigned short g_wot16[DD * DD];   // Wo^T as fp16
__device__ unsigned short g_wt[DD * DD];      // WT = (2048*Wv@Wo)^T as fp16
__device__ float g_bpart[8 * DD];             // bias j-group partials

// ---------------------------------------------------------------------------
// asm helpers (arch-neutral: mma.sync / ldmatrix / cp.async;
// tcgen05 unusable — harness PTX target is sm_103, not sm_103a)
// ---------------------------------------------------------------------------
__device__ __forceinline__ uint32_t smem_u32(const void* p) {
    uint32_t a;
    asm("{ .reg .u64 t; cvta.to.shared.u64 t, %1; cvt.u32.u64 %0, t; }" : "=r"(a) : "l"(p));
    return a;
}
#define CP16(dst, src) \
    asm volatile("cp.async.cg.shared.global [%0], [%1], 16;" :: "r"(dst), "l"(src))
#define CP_COMMIT()  asm volatile("cp.async.commit_group;" ::: "memory")
#define CP_WAIT1()   asm volatile("cp.async.wait_group 1;" ::: "memory")
#define CP_WAIT0()   asm volatile("cp.async.wait_group 0;" ::: "memory")

__device__ __forceinline__ void ldsm4(uint32_t& r0, uint32_t& r1, uint32_t& r2, uint32_t& r3,
                                      uint32_t addr) {
    asm volatile("ldmatrix.sync.aligned.m8n8.x4.shared.b16 {%0,%1,%2,%3}, [%4];"
                 : "=r"(r0), "=r"(r1), "=r"(r2), "=r"(r3) : "r"(addr));
}
__device__ __forceinline__ void mma_f16(float c[4], const uint32_t a[4], const uint32_t b[2]) {
    asm volatile(
        "mma.sync.aligned.m16n8k16.row.col.f32.f16.f16.f32 "
        "{%0,%1,%2,%3},{%4,%5,%6,%7},{%8,%9},{%0,%1,%2,%3};"
        : "+f"(c[0]), "+f"(c[1]), "+f"(c[2]), "+f"(c[3])
        : "r"(a[0]), "r"(a[1]), "r"(a[2]), "r"(a[3]), "r"(b[0]), "r"(b[1]));
}
__device__ __forceinline__ uint32_t pack_f16x2(float v0, float v1) {
    uint32_t r;
    asm("cvt.rn.f16x2.f32 %0, %1, %2;" : "=r"(r) : "f"(v1), "f"(v0));
    return r;
}

// ---------------------------------------------------------------------------
// Fused prep kernel (one launch, blocks partitioned by role):
//   [0,2048)         x -> fp16              (4 float4 / thread)
//   [2048,2176)      Wv -> fp16
//   [2176,3200)      Wo^T -> fp16           (32x32 transpose tiles)
//   [3200,3456)      bias partials: bpart[g][n] = sum_{j in g} bv[j]*Wo[j][n]
//                    (8 j-groups x 32 n-blocks; final reduce + bo folded into
//                     the main GEMM epilogue)
// ---------------------------------------------------------------------------
#define PREP_X_BLKS   2048
#define PREP_WV_BLKS  128
#define PREP_WOT_BLKS 1024
#define PREP_B_BLKS   256
#define PREP_BLKS (PREP_X_BLKS + PREP_WV_BLKS + PREP_WOT_BLKS + PREP_B_BLKS)

__global__ __launch_bounds__(256)
void prep_kernel(const float4* __restrict__ x,
                 const float4* __restrict__ Wv,
                 const float*  __restrict__ Wo,
                 const float*  __restrict__ bv,
                 uint2* __restrict__ xh, uint2* __restrict__ wv16,
                 unsigned short* __restrict__ wot16, float* __restrict__ bpart) {
    const int bid = blockIdx.x;
    const int tid = threadIdx.x;

    if (bid < PREP_X_BLKS) {
        // x convert: 1024 float4 per block, 4 independent per thread
        int base = bid * 1024 + tid;
        float4 v0 = x[base];
        float4 v1 = x[base + 256];
        float4 v2 = x[base + 512];
        float4 v3 = x[base + 768];
        uint2 o0 = { pack_f16x2(v0.x, v0.y), pack_f16x2(v0.z, v0.w) };
        uint2 o1 = { pack_f16x2(v1.x, v1.y), pack_f16x2(v1.z, v1.w) };
        uint2 o2 = { pack_f16x2(v2.x, v2.y), pack_f16x2(v2.z, v2.w) };
        uint2 o3 = { pack_f16x2(v3.x, v3.y), pack_f16x2(v3.z, v3.w) };
        xh[base]       = o0;
        xh[base + 256] = o1;
        xh[base + 512] = o2;
        xh[base + 768] = o3;
        return;
    }
    if (bid < PREP_X_BLKS + PREP_WV_BLKS) {
        int base = (bid - PREP_X_BLKS) * 2048 + tid;
        #pragma unroll
        for (int i = 0; i < 8; i++) {
            int idx = base + i * 256;
            float4 v = Wv[idx];
            uint2 o = { pack_f16x2(v.x, v.y), pack_f16x2(v.z, v.w) };
            wv16[idx] = o;
        }
        return;
    }
    if (bid < PREP_X_BLKS + PREP_WV_BLKS + PREP_WOT_BLKS) {
        // Wo^T tile: wot16[p][q] = (fp16) Wo[q][p]
        __shared__ float t[32][33];
        const int local = bid - (PREP_X_BLKS + PREP_WV_BLKS);
        const int bx = (local & 31) * 32;   // output row base (= src col)
        const int by = (local >> 5) * 32;   // output col base (= src row)
        const int cc = tid & 31;
        const int r0 = tid >> 5;
        #pragma unroll
        for (int i = 0; i < 4; i++) {
            int r = r0 + i * 8;
            t[r][cc] = Wo[(size_t)(by + r) * DD + bx + cc];
        }
        __syncthreads();
        #pragma unroll
        for (int i = 0; i < 4; i++) {
            int r = r0 + i * 8;
            float v = t[cc][r];             // = Wo[by+cc][bx+r]
            wot16[(size_t)(bx + r) * DD + by + cc] =
                (unsigned short)(pack_f16x2(v, 0.f) & 0xffffu);
        }
        return;
    }
    // bias partials: 256 blocks = 8 j-groups x 32 n-blocks (32 cols each).
    // Block handles 128 j's; thread (sj, nl) sums 16 j's for column n0+nl.
    {
        __shared__ float part[8][32];
        const int local = bid - (PREP_X_BLKS + PREP_WV_BLKS + PREP_WOT_BLKS);
        const int jg = local >> 5;           // 0..7
        const int n0 = (local & 31) * 32;
        const int nl = tid & 31;
        const int sj = tid >> 5;             // 0..7
        const int j0 = jg * 128 + sj * 16;
        float s = 0.f;
        #pragma unroll
        for (int j = 0; j < 16; j++)
            s += bv[j0 + j] * Wo[(size_t)(j0 + j) * DD + n0 + nl];
        part[sj][nl] = s;
        __syncthreads();
        if (tid < 32) {
            float acc = 0.f;
            #pragma unroll
            for (int g = 0; g < 8; g++) acc += part[g][nl];
            bpart[jg * DD + n0 + nl] = acc;
        }
    }
}

// ---------------------------------------------------------------------------
// fp16 single-term GEMM (K=1024, N tile 128). Template:
//   BM:        block rows
//   WRITE_F16: epilogue writes fp16 (alpha-scaled) vs fp32 (+bias from
//              8 partials + bo, reduced in-epilogue)
// A: [M][1024] fp16 row-major; B: [n][k] fp16, k contiguous.
// 8 warps (2x4), warp tile (BM/2) x 32, 3-stage cp.async, xor-swizzled smem.
// ---------------------------------------------------------------------------
template <int BM, bool WRITE_F16>
__global__ __launch_bounds__(256, 2)
void gemm_f16(const __half* __restrict__ A, const __half* __restrict__ B,
              const float* __restrict__ bpart, const float* __restrict__ bo,
              float* __restrict__ Cf, unsigned short* __restrict__ Ch,
              float alpha) {
    constexpr int MT = BM / 32;
    constexpr int STG = (BM + 128) * 128;
    extern __shared__ char smv[];
    const uint32_t smb = smem_u32(smv);

    const int tid  = threadIdx.x;
    const int lane = tid & 31;
    const int warp = tid >> 5;
    const int wm = warp >> 2;
    const int wn = warp & 3;
    const int blockRow = blockIdx.y * BM;
    const int blockCol = blockIdx.x * 128;

    const int l7  = lane & 7;
    const int lm  = lane & 15;
    const int hi4 = lane >> 4;

    auto issue = [&](int t, int buf) {
        const int k0 = t << 6;
        const uint32_t aB = smb + buf * STG;
        const uint32_t bB = aB + BM * 128;
        #pragma unroll
        for (int j = 0; j < BM / 32; j++) {
            int idx = j * 256 + tid;
            int row = idx >> 3, cc = idx & 7;
            uint32_t dst = aB + row * 128 + ((cc ^ (row & 7)) << 4);
            CP16(dst, A + (size_t)(blockRow + row) * DD + k0 + cc * 8);
        }
        #pragma unroll
        for (int j = 0; j < 4; j++) {
            int idx = j * 256 + tid;
            int row = idx >> 3, cc = idx & 7;
            uint32_t dst = bB + row * 128 + ((cc ^ (row & 7)) << 4);
            CP16(dst, B + (size_t)(blockCol + row) * DD + k0 + cc * 8);
        }
        CP_COMMIT();
    };

    float acc[MT][4][4];
    #pragma unroll
    for (int mt = 0; mt < MT; mt++)
        #pragma unroll
        for (int nt = 0; nt < 4; nt++)
            #pragma unroll
            for (int i = 0; i < 4; i++)
                acc[mt][nt][i] = 0.f;

    const int NT = 16;
    issue(0, 0);
    issue(1, 1);

    for (int t = 0; t < NT; t++) {
        const int buf = t % 3;
        if (t < NT - 1) CP_WAIT1(); else CP_WAIT0();
        __syncthreads();
        const uint32_t aB = smb + buf * STG;
        const uint32_t bB = aB + BM * 128;

        #pragma unroll
        for (int ks = 0; ks < 4; ks++) {
            uint32_t a[MT][4], b[4][2];
            #pragma unroll
            for (int mt = 0; mt < MT; mt++) {
                int m = wm * (BM / 2) + mt * 16 + lm;
                uint32_t ad = aB + m * 128 + ((((ks * 2 + hi4)) ^ l7) << 4);
                ldsm4(a[mt][0], a[mt][1], a[mt][2], a[mt][3], ad);
            }
            #pragma unroll
            for (int p = 0; p < 2; p++) {
                int im = lane >> 3;
                int nt = p * 2 + (im >> 1);
                int ch = (ks * 2 + (im & 1)) ^ l7;
                int n  = wn * 32 + nt * 8 + l7;
                uint32_t bd = bB + n * 128 + (ch << 4);
                ldsm4(b[p * 2][0], b[p * 2][1], b[p * 2 + 1][0], b[p * 2 + 1][1], bd);
            }
            #pragma unroll
            for (int mt = 0; mt < MT; mt++)
                #pragma unroll
                for (int nt = 0; nt < 4; nt++)
                    mma_f16(acc[mt][nt], a[mt], b[nt]);
        }
        if (t + 2 < NT) issue(t + 2, (t + 2) % 3);
    }

    if (WRITE_F16) {
        #pragma unroll
        for (int mt = 0; mt < MT; mt++) {
            #pragma unroll
            for (int nt = 0; nt < 4; nt++) {
                const int row = blockRow + wm * (BM / 2) + mt * 16 + (lane >> 2);
                const int col = blockCol + wn * 32 + nt * 8 + 2 * (lane & 3);
                float w0 = acc[mt][nt][0] * alpha;
                float w1 = acc[mt][nt][1] * alpha;
                float w2 = acc[mt][nt][2] * alpha;
                float w3 = acc[mt][nt][3] * alpha;
                *(uint32_t*)(Ch + (size_t)row * DD + col)       = pack_f16x2(w0, w1);
                *(uint32_t*)(Ch + (size_t)(row + 8) * DD + col) = pack_f16x2(w2, w3);
            }
        }
    } else {
        // Reduce bias for this thread's 8 columns (reused across MT rows)
        float bc[4][2];
        #pragma unroll
        for (int nt = 0; nt < 4; nt++) {
            const int col = blockCol + wn * 32 + nt * 8 + 2 * (lane & 3);
            float s0 = bo[col], s1 = bo[col + 1];
            #pragma unroll
            for (int g = 0; g < 8; g++) {
                s0 += 2048.0f * bpart[g * DD + col];
                s1 += 2048.0f * bpart[g * DD + col + 1];
            }
            bc[nt][0] = s0;
            bc[nt][1] = s1;
        }
        #pragma unroll
        for (int mt = 0; mt < MT; mt++) {
            #pragma unroll
            for (int nt = 0; nt < 4; nt++) {
                const int row = blockRow + wm * (BM / 2) + mt * 16 + (lane >> 2);
                const int col = blockCol + wn * 32 + nt * 8 + 2 * (lane & 3);
                float2 v0 = make_float2(acc[mt][nt][0] + bc[nt][0],
                                        acc[mt][nt][1] + bc[nt][1]);
                float2 v1 = make_float2(acc[mt][nt][2] + bc[nt][0],
                                        acc[mt][nt][3] + bc[nt][1]);
                *(float2*)(Cf + (size_t)row * DD + col)       = v0;
                *(float2*)(Cf + (size_t)(row + 8) * DD + col) = v1;
            }
        }
    }
}

// ---------------------------------------------------------------------------
// Launch:  out = x @ (2048*Wv@Wo) + (2048*bv@Wo + bo)
// (encoder_x/Wq/bq/Wk/bk dead: softmax rows sum to 1; the reference einsum
// contracts both q and k, so scores contribute exactly L = 2048.)
// All-fp16 tensor path (measured rel_err 4.2e-4 < 1e-3).
// ---------------------------------------------------------------------------
extern "C" void kernel_launch(void* const* d_in, const int* in_sizes, int n_in,
                              void* d_out, int out_size) {
    const float* x  = (const float*)d_in[0];
    const float* Wv = (const float*)d_in[6];
    const float* bv = (const float*)d_in[7];
    const float* Wo = (const float*)d_in[8];
    const float* bo = (const float*)d_in[9];
    float* out = (float*)d_out;

    unsigned short *xh, *wv16, *wot16, *wt;
    float *bp;
    cudaGetSymbolAddress((void**)&xh,    g_xh);
    cudaGetSymbolAddress((void**)&wv16,  g_wv16);
    cudaGetSymbolAddress((void**)&wot16, g_wot16);
    cudaGetSymbolAddress((void**)&wt,    g_wt);
    cudaGetSymbolAddress((void**)&bp,    g_bpart);

    constexpr int SMEM64  = (64 + 128) * 128 * 3;    // 73728
    constexpr int SMEM128 = (128 + 128) * 128 * 3;   // 98304
    cudaFuncSetAttribute(gemm_f16<64, true>,
                         cudaFuncAttributeMaxDynamicSharedMemorySize, SMEM64);
    cudaFuncSetAttribute(gemm_f16<128, false>,
                         cudaFuncAttributeMaxDynamicSharedMemorySize, SMEM128);

    // 1) fused prep: x->fp16, Wv->fp16, Wo^T->fp16, bias partials
    prep_kernel<<<PREP_BLKS, 256>>>((const float4*)x, (const float4*)Wv, Wo, bv,
                                    (uint2*)xh, (uint2*)wv16, wot16, bp);

    // 2) WT[n][k] = 2048 * sum_j Wo^T[n][j] * Wv[k][j]  -> fp16
    gemm_f16<64, true><<<dim3(8, 16), 256, SMEM64>>>(
        (const __half*)wot16, (const __half*)wv16, nullptr, nullptr,
        nullptr, wt, 2048.0f);

    // 3) out[8192][1024] = x_fp16 @ W + (2048*sum(bpart) + bo)
    gemm_f16<128, false><<<dim3(8, 64), 256, SMEM128>>>(
        (const __half*)xh, (const __half*)wt, bp, bo, out, nullptr, 1.0f);
}

// round 11
// speedup vs baseline: 1.4063x; 1.4063x over previous
#include <cuda_runtime.h>
#include <cuda_fp16.h>
#include <cstdint>
#include <cstddef>

// Problem constants
#define DD 1024
#define MROWS 8192

// ---------------------------------------------------------------------------
// Device scratch (allocation-free rule: __device__ globals)
// ---------------------------------------------------------------------------
__device__ unsigned short g_xh[MROWS * DD];   // x as fp16 (16MB)
__device__ unsigned short g_wv16[DD * DD];    // Wv as fp16
__device__ unsigned short g_wot16[DD * DD];   // Wo^T as fp16
__device__ unsigned short g_wt[DD * DD];      // WT = (2048*Wv@Wo)^T as fp16
__device__ float g_bpart[8 * DD];             // bias j-group partials
__device__ float g_c[DD];                     // 2048*(bv@Wo) + bo

// ---------------------------------------------------------------------------
// asm helpers (arch-neutral: mma.sync / ldmatrix / cp.async;
// tcgen05 unusable — harness PTX target is sm_103, not sm_103a)
// ---------------------------------------------------------------------------
__device__ __forceinline__ uint32_t smem_u32(const void* p) {
    uint32_t a;
    asm("{ .reg .u64 t; cvta.to.shared.u64 t, %1; cvt.u32.u64 %0, t; }" : "=r"(a) : "l"(p));
    return a;
}
#define CP16(dst, src) \
    asm volatile("cp.async.cg.shared.global [%0], [%1], 16;" :: "r"(dst), "l"(src))
#define CP_COMMIT()  asm volatile("cp.async.commit_group;" ::: "memory")
#define CP_WAIT1()   asm volatile("cp.async.wait_group 1;" ::: "memory")
#define CP_WAIT0()   asm volatile("cp.async.wait_group 0;" ::: "memory")

__device__ __forceinline__ void ldsm4(uint32_t& r0, uint32_t& r1, uint32_t& r2, uint32_t& r3,
                                      uint32_t addr) {
    asm volatile("ldmatrix.sync.aligned.m8n8.x4.shared.b16 {%0,%1,%2,%3}, [%4];"
                 : "=r"(r0), "=r"(r1), "=r"(r2), "=r"(r3) : "r"(addr));
}
__device__ __forceinline__ void mma_f16(float c[4], const uint32_t a[4], const uint32_t b[2]) {
    asm volatile(
        "mma.sync.aligned.m16n8k16.row.col.f32.f16.f16.f32 "
        "{%0,%1,%2,%3},{%4,%5,%6,%7},{%8,%9},{%0,%1,%2,%3};"
        : "+f"(c[0]), "+f"(c[1]), "+f"(c[2]), "+f"(c[3])
        : "r"(a[0]), "r"(a[1]), "r"(a[2]), "r"(a[3]), "r"(b[0]), "r"(b[1]));
}
__device__ __forceinline__ uint32_t pack_f16x2(float v0, float v1) {
    uint32_t r;
    asm("cvt.rn.f16x2.f32 %0, %1, %2;" : "=r"(r) : "f"(v1), "f"(v0));
    return r;
}

// ---------------------------------------------------------------------------
// Fused prep kernel (one launch, blocks partitioned by role):
//   [0,2048)         x -> fp16              (4 float4 / thread)
//   [2048,2176)      Wv -> fp16
//   [2176,3200)      Wo^T -> fp16           (32x32 transpose tiles)
//   [3200,3456)      bias partials: bpart[g][n] = sum_{j in g} bv[j]*Wo[j][n]
//                    (final reduce + bo happens in the W-GEMM launch, blk 0)
// ---------------------------------------------------------------------------
#define PREP_X_BLKS   2048
#define PREP_WV_BLKS  128
#define PREP_WOT_BLKS 1024
#define PREP_B_BLKS   256
#define PREP_BLKS (PREP_X_BLKS + PREP_WV_BLKS + PREP_WOT_BLKS + PREP_B_BLKS)

__global__ __launch_bounds__(256)
void prep_kernel(const float4* __restrict__ x,
                 const float4* __restrict__ Wv,
                 const float*  __restrict__ Wo,
                 const float*  __restrict__ bv,
                 uint2* __restrict__ xh, uint2* __restrict__ wv16,
                 unsigned short* __restrict__ wot16, float* __restrict__ bpart) {
    const int bid = blockIdx.x;
    const int tid = threadIdx.x;

    if (bid < PREP_X_BLKS) {
        // x convert: 1024 float4 per block, 4 independent per thread
        int base = bid * 1024 + tid;
        float4 v0 = x[base];
        float4 v1 = x[base + 256];
        float4 v2 = x[base + 512];
        float4 v3 = x[base + 768];
        uint2 o0 = { pack_f16x2(v0.x, v0.y), pack_f16x2(v0.z, v0.w) };
        uint2 o1 = { pack_f16x2(v1.x, v1.y), pack_f16x2(v1.z, v1.w) };
        uint2 o2 = { pack_f16x2(v2.x, v2.y), pack_f16x2(v2.z, v2.w) };
        uint2 o3 = { pack_f16x2(v3.x, v3.y), pack_f16x2(v3.z, v3.w) };
        xh[base]       = o0;
        xh[base + 256] = o1;
        xh[base + 512] = o2;
        xh[base + 768] = o3;
        return;
    }
    if (bid < PREP_X_BLKS + PREP_WV_BLKS) {
        int base = (bid - PREP_X_BLKS) * 2048 + tid;
        #pragma unroll
        for (int i = 0; i < 8; i++) {
            int idx = base + i * 256;
            float4 v = Wv[idx];
            uint2 o = { pack_f16x2(v.x, v.y), pack_f16x2(v.z, v.w) };
            wv16[idx] = o;
        }
        return;
    }
    if (bid < PREP_X_BLKS + PREP_WV_BLKS + PREP_WOT_BLKS) {
        // Wo^T tile: wot16[p][q] = (fp16) Wo[q][p]
        __shared__ float t[32][33];
        const int local = bid - (PREP_X_BLKS + PREP_WV_BLKS);
        const int bx = (local & 31) * 32;   // output row base (= src col)
        const int by = (local >> 5) * 32;   // output col base (= src row)
        const int cc = tid & 31;
        const int r0 = tid >> 5;
        #pragma unroll
        for (int i = 0; i < 4; i++) {
            int r = r0 + i * 8;
            t[r][cc] = Wo[(size_t)(by + r) * DD + bx + cc];
        }
        __syncthreads();
        #pragma unroll
        for (int i = 0; i < 4; i++) {
            int r = r0 + i * 8;
            float v = t[cc][r];             // = Wo[by+cc][bx+r]
            wot16[(size_t)(bx + r) * DD + by + cc] =
                (unsigned short)(pack_f16x2(v, 0.f) & 0xffffu);
        }
        return;
    }
    // bias partials: 256 blocks = 8 j-groups x 32 n-blocks (32 cols each).
    {
        __shared__ float part[8][32];
        const int local = bid - (PREP_X_BLKS + PREP_WV_BLKS + PREP_WOT_BLKS);
        const int jg = local >> 5;           // 0..7
        const int n0 = (local & 31) * 32;
        const int nl = tid & 31;
        const int sj = tid >> 5;             // 0..7
        const int j0 = jg * 128 + sj * 16;
        float s = 0.f;
        #pragma unroll
        for (int j = 0; j < 16; j++)
            s += bv[j0 + j] * Wo[(size_t)(j0 + j) * DD + n0 + nl];
        part[sj][nl] = s;
        __syncthreads();
        if (tid < 32) {
            float acc = 0.f;
            #pragma unroll
            for (int g = 0; g < 8; g++) acc += part[g][nl];
            bpart[jg * DD + n0 + nl] = acc;
        }
    }
}

// ---------------------------------------------------------------------------
// fp16 single-term GEMM (K=1024, N tile 128). Template:
//   BM:        block rows
//   WRITE_F16: epilogue writes fp16 (alpha-scaled) vs fp32 (+bias c[n])
// In the WRITE_F16 (W-GEMM) variant, block (0,0) additionally reduces the
// bias partials into c[] BEFORE its GEMM work (ready for the next launch).
// ---------------------------------------------------------------------------
template <int BM, bool WRITE_F16>
__global__ __launch_bounds__(256, 2)
void gemm_f16(const __half* __restrict__ A, const __half* __restrict__ B,
              const float* __restrict__ bias, float* __restrict__ Cf,
              unsigned short* __restrict__ Ch, float alpha,
              const float* __restrict__ bpart, const float* __restrict__ bo,
              float* __restrict__ cvec) {
    constexpr int MT = BM / 32;
    constexpr int STG = (BM + 128) * 128;
    extern __shared__ char smv[];
    const uint32_t smb = smem_u32(smv);

    const int tid  = threadIdx.x;
    const int lane = tid & 31;
    const int warp = tid >> 5;
    const int wm = warp >> 2;
    const int wn = warp & 3;
    const int blockRow = blockIdx.y * BM;
    const int blockCol = blockIdx.x * 128;

    // W-GEMM side job: block (0,0) reduces bias partials into cvec.
    if (WRITE_F16 && blockIdx.x == 0 && blockIdx.y == 0) {
        const int n0 = tid * 4;
        float4 s = *(const float4*)(bo + n0);
        #pragma unroll
        for (int g = 0; g < 8; g++) {
            float4 pp = *(const float4*)(bpart + g * DD + n0);
            s.x += 2048.0f * pp.x;
            s.y += 2048.0f * pp.y;
            s.z += 2048.0f * pp.z;
            s.w += 2048.0f * pp.w;
        }
        *(float4*)(cvec + n0) = s;
    }

    const int l7  = lane & 7;
    const int lm  = lane & 15;
    const int hi4 = lane >> 4;

    auto issue = [&](int t, int buf) {
        const int k0 = t << 6;
        const uint32_t aB = smb + buf * STG;
        const uint32_t bB = aB + BM * 128;
        #pragma unroll
        for (int j = 0; j < BM / 32; j++) {
            int idx = j * 256 + tid;
            int row = idx >> 3, cc = idx & 7;
            uint32_t dst = aB + row * 128 + ((cc ^ (row & 7)) << 4);
            CP16(dst, A + (size_t)(blockRow + row) * DD + k0 + cc * 8);
        }
        #pragma unroll
        for (int j = 0; j < 4; j++) {
            int idx = j * 256 + tid;
            int row = idx >> 3, cc = idx & 7;
            uint32_t dst = bB + row * 128 + ((cc ^ (row & 7)) << 4);
            CP16(dst, B + (size_t)(blockCol + row) * DD + k0 + cc * 8);
        }
        CP_COMMIT();
    };

    float acc[MT][4][4];
    #pragma unroll
    for (int mt = 0; mt < MT; mt++)
        #pragma unroll
        for (int nt = 0; nt < 4; nt++)
            #pragma unroll
            for (int i = 0; i < 4; i++)
                acc[mt][nt][i] = 0.f;

    const int NT = 16;
    issue(0, 0);
    issue(1, 1);

    for (int t = 0; t < NT; t++) {
        const int buf = t % 3;
        if (t < NT - 1) CP_WAIT1(); else CP_WAIT0();
        __syncthreads();
        const uint32_t aB = smb + buf * STG;
        const uint32_t bB = aB + BM * 128;

        #pragma unroll
        for (int ks = 0; ks < 4; ks++) {
            uint32_t a[MT][4], b[4][2];
            #pragma unroll
            for (int mt = 0; mt < MT; mt++) {
                int m = wm * (BM / 2) + mt * 16 + lm;
                uint32_t ad = aB + m * 128 + ((((ks * 2 + hi4)) ^ l7) << 4);
                ldsm4(a[mt][0], a[mt][1], a[mt][2], a[mt][3], ad);
            }
            #pragma unroll
            for (int p = 0; p < 2; p++) {
                int im = lane >> 3;
                int nt = p * 2 + (im >> 1);
                int ch = (ks * 2 + (im & 1)) ^ l7;
                int n  = wn * 32 + nt * 8 + l7;
                uint32_t bd = bB + n * 128 + (ch << 4);
                ldsm4(b[p * 2][0], b[p * 2][1], b[p * 2 + 1][0], b[p * 2 + 1][1], bd);
            }
            #pragma unroll
            for (int mt = 0; mt < MT; mt++)
                #pragma unroll
                for (int nt = 0; nt < 4; nt++)
                    mma_f16(acc[mt][nt], a[mt], b[nt]);
        }
        if (t + 2 < NT) issue(t + 2, (t + 2) % 3);
    }

    #pragma unroll
    for (int mt = 0; mt < MT; mt++) {
        #pragma unroll
        for (int nt = 0; nt < 4; nt++) {
            const int row = blockRow + wm * (BM / 2) + mt * 16 + (lane >> 2);
            const int col = blockCol + wn * 32 + nt * 8 + 2 * (lane & 3);
            if (WRITE_F16) {
                float w0 = acc[mt][nt][0] * alpha;
                float w1 = acc[mt][nt][1] * alpha;
                float w2 = acc[mt][nt][2] * alpha;
                float w3 = acc[mt][nt][3] * alpha;
                *(uint32_t*)(Ch + (size_t)row * DD + col)       = pack_f16x2(w0, w1);
                *(uint32_t*)(Ch + (size_t)(row + 8) * DD + col) = pack_f16x2(w2, w3);
            } else {
                float b0 = bias[col], b1 = bias[col + 1];
                float2 v0 = make_float2(acc[mt][nt][0] + b0, acc[mt][nt][1] + b1);
                float2 v1 = make_float2(acc[mt][nt][2] + b0, acc[mt][nt][3] + b1);
                *(float2*)(Cf + (size_t)row * DD + col)       = v0;
                *(float2*)(Cf + (size_t)(row + 8) * DD + col) = v1;
            }
        }
    }
}

// ---------------------------------------------------------------------------
// Launch:  out = x @ (2048*Wv@Wo) + (2048*bv@Wo + bo)
// (encoder_x/Wq/bq/Wk/bk dead: softmax rows sum to 1; the reference einsum
// contracts both q and k, so scores contribute exactly L = 2048.)
// All-fp16 tensor path (measured rel_err 4.2e-4 < 1e-3).
// ---------------------------------------------------------------------------
extern "C" void kernel_launch(void* const* d_in, const int* in_sizes, int n_in,
                              void* d_out, int out_size) {
    const float* x  = (const float*)d_in[0];
    const float* Wv = (const float*)d_in[6];
    const float* bv = (const float*)d_in[7];
    const float* Wo = (const float*)d_in[8];
    const float* bo = (const float*)d_in[9];
    float* out = (float*)d_out;

    unsigned short *xh, *wv16, *wot16, *wt;
    float *bp, *c;
    cudaGetSymbolAddress((void**)&xh,    g_xh);
    cudaGetSymbolAddress((void**)&wv16,  g_wv16);
    cudaGetSymbolAddress((void**)&wot16, g_wot16);
    cudaGetSymbolAddress((void**)&wt,    g_wt);
    cudaGetSymbolAddress((void**)&bp,    g_bpart);
    cudaGetSymbolAddress((void**)&c,     g_c);

    constexpr int SMEM64  = (64 + 128) * 128 * 3;    // 73728
    constexpr int SMEM128 = (128 + 128) * 128 * 3;   // 98304
    cudaFuncSetAttribute(gemm_f16<64, true>,
                         cudaFuncAttributeMaxDynamicSharedMemorySize, SMEM64);
    cudaFuncSetAttribute(gemm_f16<128, false>,
                         cudaFuncAttributeMaxDynamicSharedMemorySize, SMEM128);

    // 1) fused prep: x->fp16, Wv->fp16, Wo^T->fp16, bias partials
    prep_kernel<<<PREP_BLKS, 256>>>((const float4*)x, (const float4*)Wv, Wo, bv,
                                    (uint2*)xh, (uint2*)wv16, wot16, bp);

    // 2) WT[n][k] = 2048 * sum_j Wo^T[n][j] * Wv[k][j] -> fp16
    //    (block (0,0) also reduces bias partials into c)
    gemm_f16<64, true><<<dim3(8, 16), 256, SMEM64>>>(
        (const __half*)wot16, (const __half*)wv16, nullptr, nullptr,
        wt, 2048.0f, bp, bo, c);

    // 3) out[8192][1024] = x_fp16 @ W + c
    gemm_f16<128, false><<<dim3(8, 64), 256, SMEM128>>>(
        (const __half*)xh, (const __half*)wt, c, out, nullptr, 1.0f,
        nullptr, nullptr, nullptr);
}

// round 12
// speedup vs baseline: 1.4586x; 1.0371x over previous
#include <cuda_runtime.h>
#include <cuda_fp16.h>
#include <cstdint>
#include <cstddef>

// Problem constants
#define DD 1024
#define MROWS 8192

// ---------------------------------------------------------------------------
// Device scratch (allocation-free rule: __device__ globals)
// ---------------------------------------------------------------------------
__device__ unsigned short g_xh[MROWS * DD];   // x as fp16 (16MB)
__device__ unsigned short g_wv16[DD * DD];    // Wv as fp16
__device__ unsigned short g_wot16[DD * DD];   // Wo^T as fp16
__device__ unsigned short g_wt[DD * DD];      // WT = (2048*Wv@Wo)^T as fp16
__device__ float g_bpart[8 * DD];             // bias j-group partials
__device__ float g_c[DD];                     // 2048*(bv@Wo) + bo

// ---------------------------------------------------------------------------
// asm helpers (arch-neutral: mma.sync / ldmatrix / cp.async;
// tcgen05 unusable — harness PTX target is sm_103, not sm_103a)
// ---------------------------------------------------------------------------
__device__ __forceinline__ uint32_t smem_u32(const void* p) {
    uint32_t a;
    asm("{ .reg .u64 t; cvta.to.shared.u64 t, %1; cvt.u32.u64 %0, t; }" : "=r"(a) : "l"(p));
    return a;
}
#define CP16(dst, src) \
    asm volatile("cp.async.cg.shared.global [%0], [%1], 16;" :: "r"(dst), "l"(src))
#define CP_COMMIT()  asm volatile("cp.async.commit_group;" ::: "memory")
#define CP_WAIT1()   asm volatile("cp.async.wait_group 1;" ::: "memory")
#define CP_WAIT0()   asm volatile("cp.async.wait_group 0;" ::: "memory")

__device__ __forceinline__ void ldsm4(uint32_t& r0, uint32_t& r1, uint32_t& r2, uint32_t& r3,
                                      uint32_t addr) {
    asm volatile("ldmatrix.sync.aligned.m8n8.x4.shared.b16 {%0,%1,%2,%3}, [%4];"
                 : "=r"(r0), "=r"(r1), "=r"(r2), "=r"(r3) : "r"(addr));
}
__device__ __forceinline__ void mma_f16(float c[4], const uint32_t a[4], const uint32_t b[2]) {
    asm volatile(
        "mma.sync.aligned.m16n8k16.row.col.f32.f16.f16.f32 "
        "{%0,%1,%2,%3},{%4,%5,%6,%7},{%8,%9},{%0,%1,%2,%3};"
        : "+f"(c[0]), "+f"(c[1]), "+f"(c[2]), "+f"(c[3])
        : "r"(a[0]), "r"(a[1]), "r"(a[2]), "r"(a[3]), "r"(b[0]), "r"(b[1]));
}
__device__ __forceinline__ uint32_t pack_f16x2(float v0, float v1) {
    uint32_t r;
    asm("cvt.rn.f16x2.f32 %0, %1, %2;" : "=r"(r) : "f"(v1), "f"(v0));
    return r;
}

// ---------------------------------------------------------------------------
// W-side prep kernel (one launch, blocks partitioned by role):
//   [0,128)      Wv -> fp16
//   [128,1152)   Wo^T -> fp16           (32x32 transpose tiles)
//   [1152,1408)  bias partials: bpart[g][n] = sum_{j in g} bv[j]*Wo[j][n]
// (x -> fp16 conversion rides along with the W-GEMM launch instead: the
//  W-GEMM has only 128 tile-blocks and would leave the chip idle.)
// ---------------------------------------------------------------------------
#define PREP_WV_BLKS  128
#define PREP_WOT_BLKS 1024
#define PREP_B_BLKS   256
#define PREP_BLKS (PREP_WV_BLKS + PREP_WOT_BLKS + PREP_B_BLKS)

__global__ __launch_bounds__(256)
void prep_w_kernel(const float4* __restrict__ Wv,
                   const float*  __restrict__ Wo,
                   const float*  __restrict__ bv,
                   uint2* __restrict__ wv16,
                   unsigned short* __restrict__ wot16,
                   float* __restrict__ bpart) {
    const int bid = blockIdx.x;
    const int tid = threadIdx.x;

    if (bid < PREP_WV_BLKS) {
        int base = bid * 2048 + tid;
        #pragma unroll
        for (int i = 0; i < 8; i++) {
            int idx = base + i * 256;
            float4 v = Wv[idx];
            uint2 o = { pack_f16x2(v.x, v.y), pack_f16x2(v.z, v.w) };
            wv16[idx] = o;
        }
        return;
    }
    if (bid < PREP_WV_BLKS + PREP_WOT_BLKS) {
        // Wo^T tile: wot16[p][q] = (fp16) Wo[q][p]
        __shared__ float t[32][33];
        const int local = bid - PREP_WV_BLKS;
        const int bx = (local & 31) * 32;   // output row base (= src col)
        const int by = (local >> 5) * 32;   // output col base (= src row)
        const int cc = tid & 31;
        const int r0 = tid >> 5;
        #pragma unroll
        for (int i = 0; i < 4; i++) {
            int r = r0 + i * 8;
            t[r][cc] = Wo[(size_t)(by + r) * DD + bx + cc];
        }
        __syncthreads();
        #pragma unroll
        for (int i = 0; i < 4; i++) {
            int r = r0 + i * 8;
            float v = t[cc][r];             // = Wo[by+cc][bx+r]
            wot16[(size_t)(bx + r) * DD + by + cc] =
                (unsigned short)(pack_f16x2(v, 0.f) & 0xffffu);
        }
        return;
    }
    // bias partials: 256 blocks = 8 j-groups x 32 n-blocks (32 cols each).
    {
        __shared__ float part[8][32];
        const int local = bid - (PREP_WV_BLKS + PREP_WOT_BLKS);
        const int jg = local >> 5;           // 0..7
        const int n0 = (local & 31) * 32;
        const int nl = tid & 31;
        const int sj = tid >> 5;             // 0..7
        const int j0 = jg * 128 + sj * 16;
        float s = 0.f;
        #pragma unroll
        for (int j = 0; j < 16; j++)
            s += bv[j0 + j] * Wo[(size_t)(j0 + j) * DD + n0 + nl];
        part[sj][nl] = s;
        __syncthreads();
        if (tid < 32) {
            float acc = 0.f;
            #pragma unroll
            for (int g = 0; g < 8; g++) acc += part[g][nl];
            bpart[jg * DD + n0 + nl] = acc;
        }
    }
}

// ---------------------------------------------------------------------------
// Fused W-GEMM + x-convert launch (1D grid):
//   blocks [0,128):     WT[n][k] = 2048 * sum_j Wo^T[n][j]*Wv[k][j] -> fp16
//                       (BM=64 tile GEMM; block 0 also reduces bpart -> c)
//   blocks [128,2176):  x -> fp16 (2048 converter blocks fill idle SMs)
// ---------------------------------------------------------------------------
#define WG_TILE_BLKS 128
#define WG_X_BLKS    2048
#define WG_BLKS (WG_TILE_BLKS + WG_X_BLKS)
#define WG_SMEM ((64 + 128) * 128 * 3)   // 73728

__global__ __launch_bounds__(256, 2)
void wgemm_xconv_kernel(const __half* __restrict__ A,   // wot16 [n][j]
                        const __half* __restrict__ B,   // wv16  [k][j]
                        unsigned short* __restrict__ Ch, // wt out fp16
                        const float* __restrict__ bpart,
                        const float* __restrict__ bo,
                        float* __restrict__ cvec,
                        const float4* __restrict__ x,
                        uint2* __restrict__ xh) {
    const int bid = blockIdx.x;
    const int tid = threadIdx.x;

    if (bid >= WG_TILE_BLKS) {
        // ---- x -> fp16 converter role
        int base = (bid - WG_TILE_BLKS) * 1024 + tid;
        float4 v0 = x[base];
        float4 v1 = x[base + 256];
        float4 v2 = x[base + 512];
        float4 v3 = x[base + 768];
        uint2 o0 = { pack_f16x2(v0.x, v0.y), pack_f16x2(v0.z, v0.w) };
        uint2 o1 = { pack_f16x2(v1.x, v1.y), pack_f16x2(v1.z, v1.w) };
        uint2 o2 = { pack_f16x2(v2.x, v2.y), pack_f16x2(v2.z, v2.w) };
        uint2 o3 = { pack_f16x2(v3.x, v3.y), pack_f16x2(v3.z, v3.w) };
        xh[base]       = o0;
        xh[base + 256] = o1;
        xh[base + 512] = o2;
        xh[base + 768] = o3;
        return;
    }

    // ---- W-GEMM role: BM=64, tile (bx, by) = (bid & 7, bid >> 3)
    constexpr int BM = 64;
    constexpr int MT = BM / 32;              // 2
    constexpr int STG = (BM + 128) * 128;
    extern __shared__ char smv[];
    const uint32_t smb = smem_u32(smv);

    const int lane = tid & 31;
    const int warp = tid >> 5;
    const int wm = warp >> 2;
    const int wn = warp & 3;
    const int blockRow = (bid >> 3) * BM;
    const int blockCol = (bid & 7) * 128;

    // side job: block 0 reduces bias partials into cvec
    if (bid == 0) {
        const int n0 = tid * 4;
        float4 s = *(const float4*)(bo + n0);
        #pragma unroll
        for (int g = 0; g < 8; g++) {
            float4 pp = *(const float4*)(bpart + g * DD + n0);
            s.x += 2048.0f * pp.x;
            s.y += 2048.0f * pp.y;
            s.z += 2048.0f * pp.z;
            s.w += 2048.0f * pp.w;
        }
        *(float4*)(cvec + n0) = s;
    }

    const int l7  = lane & 7;
    const int lm  = lane & 15;
    const int hi4 = lane >> 4;

    auto issue = [&](int t, int buf) {
        const int k0 = t << 6;
        const uint32_t aB = smb + buf * STG;
        const uint32_t bB = aB + BM * 128;
        #pragma unroll
        for (int j = 0; j < BM / 32; j++) {
            int idx = j * 256 + tid;
            int row = idx >> 3, cc = idx & 7;
            uint32_t dst = aB + row * 128 + ((cc ^ (row & 7)) << 4);
            CP16(dst, A + (size_t)(blockRow + row) * DD + k0 + cc * 8);
        }
        #pragma unroll
        for (int j = 0; j < 4; j++) {
            int idx = j * 256 + tid;
            int row = idx >> 3, cc = idx & 7;
            uint32_t dst = bB + row * 128 + ((cc ^ (row & 7)) << 4);
            CP16(dst, B + (size_t)(blockCol + row) * DD + k0 + cc * 8);
        }
        CP_COMMIT();
    };

    float acc[MT][4][4];
    #pragma unroll
    for (int mt = 0; mt < MT; mt++)
        #pragma unroll
        for (int nt = 0; nt < 4; nt++)
            #pragma unroll
            for (int i = 0; i < 4; i++)
                acc[mt][nt][i] = 0.f;

    const int NT = 16;
    issue(0, 0);
    issue(1, 1);

    for (int t = 0; t < NT; t++) {
        const int buf = t % 3;
        if (t < NT - 1) CP_WAIT1(); else CP_WAIT0();
        __syncthreads();
        const uint32_t aB = smb + buf * STG;
        const uint32_t bB = aB + BM * 128;

        #pragma unroll
        for (int ks = 0; ks < 4; ks++) {
            uint32_t a[MT][4], b[4][2];
            #pragma unroll
            for (int mt = 0; mt < MT; mt++) {
                int m = wm * (BM / 2) + mt * 16 + lm;
                uint32_t ad = aB + m * 128 + ((((ks * 2 + hi4)) ^ l7) << 4);
                ldsm4(a[mt][0], a[mt][1], a[mt][2], a[mt][3], ad);
            }
            #pragma unroll
            for (int p = 0; p < 2; p++) {
                int im = lane >> 3;
                int nt = p * 2 + (im >> 1);
                int ch = (ks * 2 + (im & 1)) ^ l7;
                int n  = wn * 32 + nt * 8 + l7;
                uint32_t bd = bB + n * 128 + (ch << 4);
                ldsm4(b[p * 2][0], b[p * 2][1], b[p * 2 + 1][0], b[p * 2 + 1][1], bd);
            }
            #pragma unroll
            for (int mt = 0; mt < MT; mt++)
                #pragma unroll
                for (int nt = 0; nt < 4; nt++)
                    mma_f16(acc[mt][nt], a[mt], b[nt]);
        }
        if (t + 2 < NT) issue(t + 2, (t + 2) % 3);
    }

    #pragma unroll
    for (int mt = 0; mt < MT; mt++) {
        #pragma unroll
        for (int nt = 0; nt < 4; nt++) {
            const int row = blockRow + wm * (BM / 2) + mt * 16 + (lane >> 2);
            const int col = blockCol + wn * 32 + nt * 8 + 2 * (lane & 3);
            float w0 = acc[mt][nt][0] * 2048.0f;
            float w1 = acc[mt][nt][1] * 2048.0f;
            float w2 = acc[mt][nt][2] * 2048.0f;
            float w3 = acc[mt][nt][3] * 2048.0f;
            *(uint32_t*)(Ch + (size_t)row * DD + col)       = pack_f16x2(w0, w1);
            *(uint32_t*)(Ch + (size_t)(row + 8) * DD + col) = pack_f16x2(w2, w3);
        }
    }
}

// ---------------------------------------------------------------------------
// Main fp16 GEMM: out[8192][1024] = xh @ WT^T + c   (BM=128, validated 45us)
// ---------------------------------------------------------------------------
#define MAIN_SMEM ((128 + 128) * 128 * 3)   // 98304

__global__ __launch_bounds__(256, 2)
void gemm_f16_main(const __half* __restrict__ A, const __half* __restrict__ B,
                   const float* __restrict__ bias, float* __restrict__ Cf) {
    constexpr int BM = 128;
    constexpr int MT = BM / 32;              // 4
    constexpr int STG = (BM + 128) * 128;
    extern __shared__ char smv[];
    const uint32_t smb = smem_u32(smv);

    const int tid  = threadIdx.x;
    const int lane = tid & 31;
    const int warp = tid >> 5;
    const int wm = warp >> 2;
    const int wn = warp & 3;
    const int blockRow = blockIdx.y * BM;
    const int blockCol = blockIdx.x * 128;

    const int l7  = lane & 7;
    const int lm  = lane & 15;
    const int hi4 = lane >> 4;

    auto issue = [&](int t, int buf) {
        const int k0 = t << 6;
        const uint32_t aB = smb + buf * STG;
        const uint32_t bB = aB + BM * 128;
        #pragma unroll
        for (int j = 0; j < BM / 32; j++) {
            int idx = j * 256 + tid;
            int row = idx >> 3, cc = idx & 7;
            uint32_t dst = aB + row * 128 + ((cc ^ (row & 7)) << 4);
            CP16(dst, A + (size_t)(blockRow + row) * DD + k0 + cc * 8);
        }
        #pragma unroll
        for (int j = 0; j < 4; j++) {
            int idx = j * 256 + tid;
            int row = idx >> 3, cc = idx & 7;
            uint32_t dst = bB + row * 128 + ((cc ^ (row & 7)) << 4);
            CP16(dst, B + (size_t)(blockCol + row) * DD + k0 + cc * 8);
        }
        CP_COMMIT();
    };

    float acc[MT][4][4];
    #pragma unroll
    for (int mt = 0; mt < MT; mt++)
        #pragma unroll
        for (int nt = 0; nt < 4; nt++)
            #pragma unroll
            for (int i = 0; i < 4; i++)
                acc[mt][nt][i] = 0.f;

    const int NT = 16;
    issue(0, 0);
    issue(1, 1);

    for (int t = 0; t < NT; t++) {
        const int buf = t % 3;
        if (t < NT - 1) CP_WAIT1(); else CP_WAIT0();
        __syncthreads();
        const uint32_t aB = smb + buf * STG;
        const uint32_t bB = aB + BM * 128;

        #pragma unroll
        for (int ks = 0; ks < 4; ks++) {
            uint32_t a[MT][4], b[4][2];
            #pragma unroll
            for (int mt = 0; mt < MT; mt++) {
                int m = wm * (BM / 2) + mt * 16 + lm;
                uint32_t ad = aB + m * 128 + ((((ks * 2 + hi4)) ^ l7) << 4);
                ldsm4(a[mt][0], a[mt][1], a[mt][2], a[mt][3], ad);
            }
            #pragma unroll
            for (int p = 0; p < 2; p++) {
                int im = lane >> 3;
                int nt = p * 2 + (im >> 1);
                int ch = (ks * 2 + (im & 1)) ^ l7;
                int n  = wn * 32 + nt * 8 + l7;
                uint32_t bd = bB + n * 128 + (ch << 4);
                ldsm4(b[p * 2][0], b[p * 2][1], b[p * 2 + 1][0], b[p * 2 + 1][1], bd);
            }
            #pragma unroll
            for (int mt = 0; mt < MT; mt++)
                #pragma unroll
                for (int nt = 0; nt < 4; nt++)
                    mma_f16(acc[mt][nt], a[mt], b[nt]);
        }
        if (t + 2 < NT) issue(t + 2, (t + 2) % 3);
    }

    #pragma unroll
    for (int mt = 0; mt < MT; mt++) {
        #pragma unroll
        for (int nt = 0; nt < 4; nt++) {
            const int row = blockRow + wm * (BM / 2) + mt * 16 + (lane >> 2);
            const int col = blockCol + wn * 32 + nt * 8 + 2 * (lane & 3);
            float b0 = bias[col], b1 = bias[col + 1];
            float2 v0 = make_float2(acc[mt][nt][0] + b0, acc[mt][nt][1] + b1);
            float2 v1 = make_float2(acc[mt][nt][2] + b0, acc[mt][nt][3] + b1);
            *(float2*)(Cf + (size_t)row * DD + col)       = v0;
            *(float2*)(Cf + (size_t)(row + 8) * DD + col) = v1;
        }
    }
}

// ---------------------------------------------------------------------------
// Launch:  out = x @ (2048*Wv@Wo) + (2048*bv@Wo + bo)
// (encoder_x/Wq/bq/Wk/bk dead: softmax rows sum to 1; the reference einsum
// contracts both q and k, so scores contribute exactly L = 2048.)
// All-fp16 tensor path (measured rel_err 4.2e-4 < 1e-3).
// ---------------------------------------------------------------------------
extern "C" void kernel_launch(void* const* d_in, const int* in_sizes, int n_in,
                              void* d_out, int out_size) {
    const float* x  = (const float*)d_in[0];
    const float* Wv = (const float*)d_in[6];
    const float* bv = (const float*)d_in[7];
    const float* Wo = (const float*)d_in[8];
    const float* bo = (const float*)d_in[9];
    float* out = (float*)d_out;

    unsigned short *xh, *wv16, *wot16, *wt;
    float *bp, *c;
    cudaGetSymbolAddress((void**)&xh,    g_xh);
    cudaGetSymbolAddress((void**)&wv16,  g_wv16);
    cudaGetSymbolAddress((void**)&wot16, g_wot16);
    cudaGetSymbolAddress((void**)&wt,    g_wt);
    cudaGetSymbolAddress((void**)&bp,    g_bpart);
    cudaGetSymbolAddress((void**)&c,     g_c);

    cudaFuncSetAttribute(wgemm_xconv_kernel,
                         cudaFuncAttributeMaxDynamicSharedMemorySize, WG_SMEM);
    cudaFuncSetAttribute(gemm_f16_main,
                         cudaFuncAttributeMaxDynamicSharedMemorySize, MAIN_SMEM);

    // 1) W-side prep: Wv->fp16, Wo^T->fp16, bias partials (~14MB traffic)
    prep_w_kernel<<<PREP_BLKS, 256>>>((const float4*)Wv, Wo, bv,
                                      (uint2*)wv16, wot16, bp);

    // 2) W-GEMM (128 tile blocks) + x->fp16 (2048 converter blocks) fused
    wgemm_xconv_kernel<<<WG_BLKS, 256, WG_SMEM>>>(
        (const __half*)wot16, (const __half*)wv16, wt, bp, bo, c,
        (const float4*)x, (uint2*)xh);

    // 3) out[8192][1024] = xh @ WT^T + c
    gemm_f16_main<<<dim3(8, 64), 256, MAIN_SMEM>>>(
        (const __half*)xh, (const __half*)wt, c, out);
}